// round 14
// baseline (speedup 1.0000x reference)
#include <cuda_runtime.h>
#include <math.h>

#define N_WL 262144
#define NV2  (N_WL / 2)          // 131072 float2 per N-length row

#define T_REF    273.15f
#define P_REF    101325.0f
#define C_LIGHT  299792458.0f
#define K_B      1.380649e-23f
#define N_AVO    6.02214076e+23f
#define SQRT2LN2 1.1774100226f   // sqrt(2*ln 2)
#define SQRTPI   1.7724538509f   // sqrt(pi)
#define INV_SQRTPI 0.5641895835f
#define TWO_OV_PI  0.63661977237f

// LINES: nu0, strength, width, temp_exp  (row-major, 10 lines)
__constant__ float c_lines[40] = {
    254.0f, 1.15e-17f, 2.0f, 0.05f,
    280.0f, 5.0e-18f,  3.0f, 0.04f,
    310.0f, 1.9e-19f,  2.5f, 0.03f,
    940.0f, 2.5e-23f,  3.0f, 0.40f,
   1130.0f, 8.2e-24f,  2.5f, 0.35f,
   1380.0f, 1.8e-22f,  4.0f, 0.45f,
   1400.0f, 3.5e-25f,  3.0f, 0.50f,
   1600.0f, 7.8e-26f,  2.5f, 0.48f,
   2000.0f, 4.2e-24f,  4.0f, 0.52f,
   2700.0f, 1.2e-24f,  3.5f, 0.49f
};
__constant__ float c_mass[10] = {48.f,48.f,48.f,18.f,18.f,18.f,44.f,44.f,44.f,44.f};

__device__ __forceinline__ float sigmoidf_(float x) { return 1.0f / (1.0f + expf(-x)); }
__device__ __forceinline__ float siluf_(float x)    { return x * sigmoidf_(x); }
__device__ __forceinline__ float softplusf_(float x){ return fmaxf(x, 0.0f) + log1pf(expf(-fabsf(x))); }

// Voigt kernel value K(x, y), matching the reference's 3-branch Humlicek form.
// t = y - i*x
__device__ __forceinline__ float voigtK(float x, float y) {
    float ax = fabsf(x);
    float s  = ax + y;
    float t2r = y * y - x * x;     // Re(t^2)
    float t2i = -2.0f * x * y;     // Im(t^2)
    if (s >= 15.0f) {
        // w1 = Re( t * 0.5641896 / (0.5 + t^2) )
        float ar = 0.5f + t2r, ai = t2i;
        float nr = 0.5641896f * y, ni = 0.5641896f * (-x);
        return (nr * ar + ni * ai) / (ar * ar + ai * ai);
    } else if (ax >= 5.5f) {
        // w2 = Re( t * (1.410474 + u*0.5641896) / (0.75 + u*(3 + u)) ), u = t^2
        float cr = 1.410474f + 0.5641896f * t2r;
        float ci = 0.5641896f * t2i;
        float numr = y * cr + x * ci;        // Re(t*c), t=(y,-x)
        float numi = y * ci - x * cr;
        float dr = 3.0f + t2r, di = t2i;
        float udr = t2r * dr - t2i * di;
        float udi = t2r * di + t2i * dr;
        float denr = 0.75f + udr, deni = udi;
        return (numr * denr + numi * deni) / (denr * denr + deni * deni);
    } else {
        float x2 = x * x;
        return expf(-x2) * cosf(2.0f * x * y) * INV_SQRTPI
             + TWO_OV_PI * y * sinf(x2) / (x2 + y * y + 1e-10f);
    }
}

// ---------------------------------------------------------------------------
// Single fused kernel, prefetch-overlapped:
//   1) issue streaming loads (wl, biases, first 8 cw2 rows) — independent of
//      prep, they remain in flight across the prep barriers (BAR drains STS,
//      not register-destination LDGs), keeping DRAM busy during prep;
//   2) per-CTA redundant scalar prep into shared (deterministic, race-free);
//   3) consume prefetched rows, then stream the rest with front-batched
//      evict-first loads.
// ---------------------------------------------------------------------------
__global__ void __launch_bounds__(256)
k_fused(const float* __restrict__ wl,
        const float* __restrict__ pT, const float* __restrict__ pP,
        const float* __restrict__ pO3, const float* __restrict__ pH2O,
        const float* __restrict__ pCO2,
        const float* __restrict__ mix_w1, const float* __restrict__ mix_b1,
        const float* __restrict__ mix_w2, const float* __restrict__ mix_b2,
        const float2* __restrict__ mw3,   // mix_w3 as float2 rows [64][NV2]
        const float2* __restrict__ mb3,
        const float* __restrict__ cont_w1, const float* __restrict__ cont_b1,
        const float2* __restrict__ cw2,   // cont_w2 as float2 rows [32][NV2]
        const float2* __restrict__ cb2,
        float2* __restrict__ out)
{
    __shared__ float s_line[40];   // {nu0, inv_sigma, y, amp} x 10
    __shared__ float s_h[32];      // continuum hidden layer
    __shared__ float s_crs[8];     // cross[:8] (incl. continuum)
    __shared__ float s_m1[64];     // mixing layer-1 activations
    __shared__ float s_m2[64];     // mixing layer-2 activations

    const int t = threadIdx.x;
    const int gid = blockIdx.x * 256 + t;   // [0, NV2)

    // ---- early streaming prefetch (independent of prep) -----------------
    float2 w  = __ldcs(&((const float2*)wl)[gid]);
    float2 zc = __ldcs(&cb2[gid]);
    float2 zm = __ldcs(&mb3[gid]);
    float2 vbuf[8];
    #pragma unroll
    for (int k = 0; k < 8; k++) vbuf[k] = __ldcs(&cw2[k * NV2 + gid]);

    // ---- redundant per-CTA prep (overlaps with in-flight loads) ---------
    const float T = *pT;
    const float P = *pP;

    if (t < 10) {
        float nu0 = c_lines[4 * t + 0];
        float st  = c_lines[4 * t + 1];
        float wd  = c_lines[4 * t + 2];
        float te  = c_lines[4 * t + 3];
        float conc = (t < 3) ? *pO3 : (t < 6) ? *pH2O : *pCO2;

        float trat = T_REF / (T + 1e-12f);
        float strength_T = st * powf(trat, te);
        float gamma_L = wd * (P / (P_REF + 1e-12f)) * sqrtf(trat);
        float gamma_D = nu0 / C_LIGHT * sqrtf((2.0f * K_B) * T * N_AVO / (c_mass[t] + 1e-12f));
        float sigma   = gamma_D / (SQRT2LN2 + 1e-12f);
        float sig_eps = sigma + 1e-12f;

        s_line[4 * t + 0] = nu0;
        s_line[4 * t + 1] = 1.0f / sig_eps;                                // inv_sigma
        s_line[4 * t + 2] = gamma_L / sig_eps;                             // y
        s_line[4 * t + 3] = conc * strength_T / (sigma * SQRTPI + 1e-12f); // amplitude
    }
    if (t >= 32 && t < 64) {
        // cont_feat = [T/Tref, P/Pref, conc_h2o, 1, 0]
        int j = t - 32;
        float f0 = T / (T_REF + 1e-12f);
        float f1 = P / (P_REF + 1e-12f);
        float f2 = *pH2O;
        float z = cont_b1[j]
                + f0 * cont_w1[0 * 32 + j]
                + f1 * cont_w1[1 * 32 + j]
                + f2 * cont_w1[2 * 32 + j]
                + 1.0f * cont_w1[3 * 32 + j];   // feature 4 is 0
        s_h[j] = siluf_(z);
    }
    __syncthreads();

    if (t < 8) {
        float wv = wl[t];
        float cross = 0.0f;
        #pragma unroll
        for (int l = 0; l < 10; l++) {
            float x = (wv - s_line[4 * l + 0]) * s_line[4 * l + 1];
            cross += s_line[4 * l + 3] * voigtK(x, s_line[4 * l + 2]);
        }
        float z = ((const float*)cb2)[t];
        #pragma unroll
        for (int k = 0; k < 32; k++) z += s_h[k] * ((const float*)cw2)[k * N_WL + t];
        s_crs[t] = cross + softplusf_(z);
    }
    __syncthreads();

    if (t < 64) {
        // mixing MLP layer 1
        float f0 = T / (T_REF + 1e-12f);
        float f1 = P / (P_REF + 1e-12f);
        float z = mix_b1[t] + f0 * mix_w1[0 * 64 + t] + f1 * mix_w1[1 * 64 + t];
        #pragma unroll
        for (int j = 0; j < 8; j++) z += s_crs[j] * mix_w1[(2 + j) * 64 + t];
        s_m1[t] = siluf_(z);
    }
    __syncthreads();

    if (t < 64) {
        // mixing MLP layer 2
        float z = mix_b2[t];
        #pragma unroll 8
        for (int j = 0; j < 64; j++) z += s_m1[j] * mix_w2[j * 64 + t];
        s_m2[t] = siluf_(z);
    }
    __syncthreads();

    // ---- streaming phase: 2 wavelengths per thread ----------------------

    // consume prefetched continuum rows 0..7
    #pragma unroll
    for (int k = 0; k < 8; k++) {
        float h = s_h[k];
        zc.x = fmaf(h, vbuf[k].x, zc.x);
        zc.y = fmaf(h, vbuf[k].y, zc.y);
    }
    // remaining continuum rows 8..31
    #pragma unroll 8
    for (int k = 8; k < 32; k++) {
        float h = s_h[k];
        float2 v = __ldcs(&cw2[k * NV2 + gid]);
        zc.x = fmaf(h, v.x, zc.x);
        zc.y = fmaf(h, v.y, zc.y);
    }

    // mixing: m64 . mix_w3[:, i]
    #pragma unroll 16
    for (int k = 0; k < 64; k++) {
        float m = s_m2[k];
        float2 v = __ldcs(&mw3[k * NV2 + gid]);
        zm.x = fmaf(m, v.x, zm.x);
        zm.y = fmaf(m, v.y, zm.y);
    }

    // Voigt line sum (pure ALU; overlaps with final load drain)
    float c0 = 0.f, c1 = 0.f;
    #pragma unroll 1
    for (int l = 0; l < 10; l++) {
        float nu0 = s_line[4 * l + 0];
        float is  = s_line[4 * l + 1];
        float y   = s_line[4 * l + 2];
        float amp = s_line[4 * l + 3];
        c0 += amp * voigtK((w.x - nu0) * is, y);
        c1 += amp * voigtK((w.y - nu0) * is, y);
    }

    c0 += softplusf_(zc.x);
    c1 += softplusf_(zc.y);

    float2 o;
    o.x = c0 * (1.0f + 0.1f * (sigmoidf_(zm.x) - 0.5f));
    o.y = c1 * (1.0f + 0.1f * (sigmoidf_(zm.y) - 0.5f));
    __stcs(&out[gid], o);
}

// ---------------------------------------------------------------------------
extern "C" void kernel_launch(void* const* d_in, const int* in_sizes, int n_in,
                              void* d_out, int out_size)
{
    const float* wl   = (const float*)d_in[0];
    const float* pT   = (const float*)d_in[1];
    const float* pP   = (const float*)d_in[2];
    const float* pO3  = (const float*)d_in[3];
    const float* pH2O = (const float*)d_in[4];
    const float* pCO2 = (const float*)d_in[5];
    const float* mw1  = (const float*)d_in[6];
    const float* mb1  = (const float*)d_in[7];
    const float* mw2  = (const float*)d_in[8];
    const float* mb2  = (const float*)d_in[9];
    const float* mw3  = (const float*)d_in[10];
    const float* mb3  = (const float*)d_in[11];
    const float* cw1  = (const float*)d_in[12];
    const float* cb1  = (const float*)d_in[13];
    const float* cw2  = (const float*)d_in[14];
    const float* cb2  = (const float*)d_in[15];

    k_fused<<<NV2 / 256, 256>>>(wl, pT, pP, pO3, pH2O, pCO2,
                                mw1, mb1, mw2, mb2,
                                (const float2*)mw3, (const float2*)mb3,
                                cw1, cb1,
                                (const float2*)cw2, (const float2*)cb2,
                                (float2*)d_out);
}

// round 16
// speedup vs baseline: 1.0986x; 1.0986x over previous
#include <cuda_runtime.h>
#include <math.h>

#define N_WL 262144
#define NV2  (N_WL / 2)          // 131072 float2 per N-length row

#define T_REF    273.15f
#define P_REF    101325.0f
#define C_LIGHT  299792458.0f
#define K_B      1.380649e-23f
#define N_AVO    6.02214076e+23f
#define SQRT2LN2 1.1774100226f   // sqrt(2*ln 2)
#define SQRTPI   1.7724538509f   // sqrt(pi)
#define INV_SQRTPI 0.5641895835f
#define TWO_OV_PI  0.63661977237f

// LINES: nu0, strength, width, temp_exp  (row-major, 10 lines)
__constant__ float c_lines[40] = {
    254.0f, 1.15e-17f, 2.0f, 0.05f,
    280.0f, 5.0e-18f,  3.0f, 0.04f,
    310.0f, 1.9e-19f,  2.5f, 0.03f,
    940.0f, 2.5e-23f,  3.0f, 0.40f,
   1130.0f, 8.2e-24f,  2.5f, 0.35f,
   1380.0f, 1.8e-22f,  4.0f, 0.45f,
   1400.0f, 3.5e-25f,  3.0f, 0.50f,
   1600.0f, 7.8e-26f,  2.5f, 0.48f,
   2000.0f, 4.2e-24f,  4.0f, 0.52f,
   2700.0f, 1.2e-24f,  3.5f, 0.49f
};
__constant__ float c_mass[10] = {48.f,48.f,48.f,18.f,18.f,18.f,44.f,44.f,44.f,44.f};

__device__ __forceinline__ float sigmoidf_(float x) { return 1.0f / (1.0f + expf(-x)); }
__device__ __forceinline__ float siluf_(float x)    { return x * sigmoidf_(x); }
__device__ __forceinline__ float softplusf_(float x){ return fmaxf(x, 0.0f) + log1pf(expf(-fabsf(x))); }

// Voigt kernel value K(x, y), matching the reference's 3-branch Humlicek form.
// t = y - i*x
__device__ __forceinline__ float voigtK(float x, float y) {
    float ax = fabsf(x);
    float s  = ax + y;
    float t2r = y * y - x * x;     // Re(t^2)
    float t2i = -2.0f * x * y;     // Im(t^2)
    if (s >= 15.0f) {
        float ar = 0.5f + t2r, ai = t2i;
        float nr = 0.5641896f * y, ni = 0.5641896f * (-x);
        return (nr * ar + ni * ai) / (ar * ar + ai * ai);
    } else if (ax >= 5.5f) {
        float cr = 1.410474f + 0.5641896f * t2r;
        float ci = 0.5641896f * t2i;
        float numr = y * cr + x * ci;
        float numi = y * ci - x * cr;
        float dr = 3.0f + t2r, di = t2i;
        float udr = t2r * dr - t2i * di;
        float udi = t2r * di + t2i * dr;
        float denr = 0.75f + udr, deni = udi;
        return (numr * denr + numi * deni) / (denr * denr + deni * deni);
    } else {
        float x2 = x * x;
        return expf(-x2) * cosf(2.0f * x * y) * INV_SQRTPI
             + TWO_OV_PI * y * sinf(x2) / (x2 + y * y + 1e-10f);
    }
}

// ---------------------------------------------------------------------------
// Single fused kernel (R12 structure, shortened prep):
//  - mix_w2 layer-2 weights (16/thread) + mix_b2 hoisted into registers at
//    kernel start: statically addressable, independent of all prep state, so
//    they are front-batched and in flight during the earlier prep phases.
//  - layer 2 parallelized across all 256 threads (4 partials x 16 terms per
//    output, combined via shared) — removes the 8-round serialized LDG chain
//    that dominated the prep prefix.
//  - streaming phase identical to the best measured kernel (R12).
// ---------------------------------------------------------------------------
__global__ void __launch_bounds__(256)
k_fused(const float* __restrict__ wl,
        const float* __restrict__ pT, const float* __restrict__ pP,
        const float* __restrict__ pO3, const float* __restrict__ pH2O,
        const float* __restrict__ pCO2,
        const float* __restrict__ mix_w1, const float* __restrict__ mix_b1,
        const float* __restrict__ mix_w2, const float* __restrict__ mix_b2,
        const float2* __restrict__ mw3,   // mix_w3 as float2 rows [64][NV2]
        const float2* __restrict__ mb3,
        const float* __restrict__ cont_w1, const float* __restrict__ cont_b1,
        const float2* __restrict__ cw2,   // cont_w2 as float2 rows [32][NV2]
        const float2* __restrict__ cb2,
        float2* __restrict__ out)
{
    __shared__ float s_line[40];    // {nu0, inv_sigma, y, amp} x 10
    __shared__ float s_h[32];       // continuum hidden layer
    __shared__ float s_crs[8];      // cross[:8] (incl. continuum)
    __shared__ float s_m1[64];      // mixing layer-1 activations
    __shared__ float s_part[256];   // layer-2 partial sums [4][64]
    __shared__ float s_m2[64];      // mixing layer-2 activations

    const int t = threadIdx.x;
    const int gid = blockIdx.x * 256 + t;   // [0, NV2)

    // ---- hoisted layer-2 weight loads (independent of all prep state) ---
    const int r = t >> 6;        // 0..3 : which 16-term chunk
    const int c = t & 63;        // 0..63: which output column
    float w2reg[16];
    #pragma unroll
    for (int j = 0; j < 16; j++)
        w2reg[j] = mix_w2[(r * 16 + j) * 64 + c];
    float b2v = (t < 64) ? mix_b2[t] : 0.0f;

    // ---- redundant per-CTA prep ----------------------------------------
    const float T = *pT;
    const float P = *pP;

    if (t < 10) {
        float nu0 = c_lines[4 * t + 0];
        float st  = c_lines[4 * t + 1];
        float wd  = c_lines[4 * t + 2];
        float te  = c_lines[4 * t + 3];
        float conc = (t < 3) ? *pO3 : (t < 6) ? *pH2O : *pCO2;

        float trat = T_REF / (T + 1e-12f);
        float strength_T = st * powf(trat, te);
        float gamma_L = wd * (P / (P_REF + 1e-12f)) * sqrtf(trat);
        float gamma_D = nu0 / C_LIGHT * sqrtf((2.0f * K_B) * T * N_AVO / (c_mass[t] + 1e-12f));
        float sigma   = gamma_D / (SQRT2LN2 + 1e-12f);
        float sig_eps = sigma + 1e-12f;

        s_line[4 * t + 0] = nu0;
        s_line[4 * t + 1] = 1.0f / sig_eps;                                // inv_sigma
        s_line[4 * t + 2] = gamma_L / sig_eps;                             // y
        s_line[4 * t + 3] = conc * strength_T / (sigma * SQRTPI + 1e-12f); // amplitude
    }
    if (t >= 32 && t < 64) {
        // cont_feat = [T/Tref, P/Pref, conc_h2o, 1, 0]
        int j = t - 32;
        float f0 = T / (T_REF + 1e-12f);
        float f1 = P / (P_REF + 1e-12f);
        float f2 = *pH2O;
        float z = cont_b1[j]
                + f0 * cont_w1[0 * 32 + j]
                + f1 * cont_w1[1 * 32 + j]
                + f2 * cont_w1[2 * 32 + j]
                + 1.0f * cont_w1[3 * 32 + j];   // feature 4 is 0
        s_h[j] = siluf_(z);
    }
    __syncthreads();

    if (t < 8) {
        float wv = wl[t];
        float cross = 0.0f;
        #pragma unroll
        for (int l = 0; l < 10; l++) {
            float x = (wv - s_line[4 * l + 0]) * s_line[4 * l + 1];
            cross += s_line[4 * l + 3] * voigtK(x, s_line[4 * l + 2]);
        }
        float z = ((const float*)cb2)[t];
        #pragma unroll
        for (int k = 0; k < 32; k++) z += s_h[k] * ((const float*)cw2)[k * N_WL + t];
        s_crs[t] = cross + softplusf_(z);
    }
    __syncthreads();

    if (t < 64) {
        // mixing MLP layer 1
        float f0 = T / (T_REF + 1e-12f);
        float f1 = P / (P_REF + 1e-12f);
        float z = mix_b1[t] + f0 * mix_w1[0 * 64 + t] + f1 * mix_w1[1 * 64 + t];
        #pragma unroll
        for (int j = 0; j < 8; j++) z += s_crs[j] * mix_w1[(2 + j) * 64 + t];
        s_m1[t] = siluf_(z);
    }
    __syncthreads();

    // layer 2: all 256 threads; weights already resident in registers.
    {
        float p = 0.0f;
        #pragma unroll
        for (int j = 0; j < 16; j++) p = fmaf(s_m1[r * 16 + j], w2reg[j], p);
        s_part[r * 64 + c] = p;
    }
    __syncthreads();

    if (t < 64) {
        float z = b2v + s_part[t] + s_part[64 + t] + s_part[128 + t] + s_part[192 + t];
        s_m2[t] = siluf_(z);
    }
    __syncthreads();

    // ---- streaming phase: 2 wavelengths per thread (identical to R12) ---

    // continuum: h32 . cont_w2[:, i]  — deep front-batched streaming loads
    float2 zc = __ldcs(&cb2[gid]);
    #pragma unroll 16
    for (int k = 0; k < 32; k++) {
        float h = s_h[k];
        float2 v = __ldcs(&cw2[k * NV2 + gid]);
        zc.x = fmaf(h, v.x, zc.x);
        zc.y = fmaf(h, v.y, zc.y);
    }

    // mixing: m64 . mix_w3[:, i]
    float2 zm = __ldcs(&mb3[gid]);
    #pragma unroll 16
    for (int k = 0; k < 64; k++) {
        float m = s_m2[k];
        float2 v = __ldcs(&mw3[k * NV2 + gid]);
        zm.x = fmaf(m, v.x, zm.x);
        zm.y = fmaf(m, v.y, zm.y);
    }

    // Voigt line sum (pure ALU; overlaps with final load drain)
    float2 w = __ldcs(&((const float2*)wl)[gid]);
    float c0 = 0.f, c1 = 0.f;
    #pragma unroll 1
    for (int l = 0; l < 10; l++) {
        float nu0 = s_line[4 * l + 0];
        float is  = s_line[4 * l + 1];
        float y   = s_line[4 * l + 2];
        float amp = s_line[4 * l + 3];
        c0 += amp * voigtK((w.x - nu0) * is, y);
        c1 += amp * voigtK((w.y - nu0) * is, y);
    }

    c0 += softplusf_(zc.x);
    c1 += softplusf_(zc.y);

    float2 o;
    o.x = c0 * (1.0f + 0.1f * (sigmoidf_(zm.x) - 0.5f));
    o.y = c1 * (1.0f + 0.1f * (sigmoidf_(zm.y) - 0.5f));
    __stcs(&out[gid], o);
}

// ---------------------------------------------------------------------------
extern "C" void kernel_launch(void* const* d_in, const int* in_sizes, int n_in,
                              void* d_out, int out_size)
{
    const float* wl   = (const float*)d_in[0];
    const float* pT   = (const float*)d_in[1];
    const float* pP   = (const float*)d_in[2];
    const float* pO3  = (const float*)d_in[3];
    const float* pH2O = (const float*)d_in[4];
    const float* pCO2 = (const float*)d_in[5];
    const float* mw1  = (const float*)d_in[6];
    const float* mb1  = (const float*)d_in[7];
    const float* mw2  = (const float*)d_in[8];
    const float* mb2  = (const float*)d_in[9];
    const float* mw3  = (const float*)d_in[10];
    const float* mb3  = (const float*)d_in[11];
    const float* cw1  = (const float*)d_in[12];
    const float* cb1  = (const float*)d_in[13];
    const float* cw2  = (const float*)d_in[14];
    const float* cb2  = (const float*)d_in[15];

    k_fused<<<NV2 / 256, 256>>>(wl, pT, pP, pO3, pH2O, pCO2,
                                mw1, mb1, mw2, mb2,
                                (const float2*)mw3, (const float2*)mb3,
                                cw1, cb1,
                                (const float2*)cw2, (const float2*)cb2,
                                (float2*)d_out);
}